// round 4
// baseline (speedup 1.0000x reference)
#include <cuda_runtime.h>
#include <cuda_bf16.h>

// BCE-with-logits mean loss:
//   loss = mean over all elems of softplus( target==0 ?  x : -x )
// where softplus(y) = max(y,0) + log(1 + exp(-|y|)).
//
// Memory-bound: 512 MB read (256 MB f32 logits + 256 MB i32 targets), 4 B write.
// Log-pairing: sum of log(1+e_i) over the 4 lanes of a float4 collapses to one
// __logf of the product -> 1.25 MUFU warp-ops per element instead of 2.

#define THREADS 256
#define BLOCKS  (148 * 16)

__global__ void bce_init_kernel(float* out) {
    *out = 0.0f;
}

__global__ __launch_bounds__(THREADS) void bce_reduce_kernel(
    const float4* __restrict__ x4,
    const int4*   __restrict__ t4,
    float* __restrict__ out,
    long long n4,          // number of float4 groups
    float inv_n)           // 1 / total element count
{
    const long long stride = (long long)gridDim.x * blockDim.x;
    long long i = (long long)blockIdx.x * blockDim.x + threadIdx.x;

    float acc = 0.0f;

    for (; i < n4; i += stride) {
        float4 x = x4[i];
        int4   t = t4[i];

        // y = (t==0) ? x : -x   (loss contribution is softplus(y))
        float y0 = (t.x == 0) ? x.x : -x.x;
        float y1 = (t.y == 0) ? x.y : -x.y;
        float y2 = (t.z == 0) ? x.z : -x.z;
        float y3 = (t.w == 0) ? x.w : -x.w;

        // max(y,0) terms
        acc += fmaxf(y0, 0.0f) + fmaxf(y1, 0.0f)
             + fmaxf(y2, 0.0f) + fmaxf(y3, 0.0f);

        // log(1+e) terms, paired: e in (0,1], product in (1,16]
        float e0 = __expf(-fabsf(y0));
        float e1 = __expf(-fabsf(y1));
        float e2 = __expf(-fabsf(y2));
        float e3 = __expf(-fabsf(y3));

        float p = (1.0f + e0) * (1.0f + e1) * (1.0f + e2) * (1.0f + e3);
        acc += __logf(p);
    }

    // warp reduce
    #pragma unroll
    for (int off = 16; off > 0; off >>= 1)
        acc += __shfl_xor_sync(0xFFFFFFFFu, acc, off);

    // cross-warp reduce in shared
    __shared__ float warp_sums[THREADS / 32];
    int lane = threadIdx.x & 31;
    int warp = threadIdx.x >> 5;
    if (lane == 0) warp_sums[warp] = acc;
    __syncthreads();

    if (warp == 0) {
        float v = (lane < THREADS / 32) ? warp_sums[lane] : 0.0f;
        #pragma unroll
        for (int off = (THREADS / 64); off > 0; off >>= 1)
            v += __shfl_xor_sync(0xFFFFFFFFu, v, off);
        if (lane == 0)
            atomicAdd(out, v * inv_n);   // pre-scale: keeps atomic partials tiny
    }
}

extern "C" void kernel_launch(void* const* d_in, const int* in_sizes, int n_in,
                              void* d_out, int out_size) {
    const float* x = (const float*)d_in[0];   // output (logits), float32
    const int*   t = (const int*)d_in[1];     // target, int32 in {0,1}
    float* out = (float*)d_out;

    long long n = (long long)in_sizes[0];     // 8192*8192, divisible by 4
    long long n4 = n / 4;
    float inv_n = 1.0f / (float)n;

    bce_init_kernel<<<1, 1>>>(out);
    bce_reduce_kernel<<<BLOCKS, THREADS>>>(
        (const float4*)x, (const int4*)t, out, n4, inv_n);
}